// round 1
// baseline (speedup 1.0000x reference)
#include <cuda_runtime.h>

#define BB   16
#define TT   4096
#define FEAT 256
#define KW   5

// Scratch (no allocations allowed): folded weights, per-row partial dots, alphas.
__device__ float g_weff[FEAT * KW];
__device__ float g_bias;
__device__ float g_p[BB * TT * KW];
__device__ float g_alphas[BB * TT];

// ---------------------------------------------------------------------------
// Kernel 1: fold lin_w into conv_w  ->  w_eff[c,k] = sum_o lin_w[o]*conv_w[o,c,k]
// Also compute the constant bias: lin_b + sum_o conv_b[o]*lin_w[o].
// ---------------------------------------------------------------------------
__global__ void fold_kernel(const float* __restrict__ conv_w,
                            const float* __restrict__ conv_b,
                            const float* __restrict__ lin_w,
                            const float* __restrict__ lin_b) {
    int j = blockIdx.x * blockDim.x + threadIdx.x;   // j = c*KW + k
    if (j < FEAT * KW) {
        float s = 0.f;
#pragma unroll 4
        for (int o = 0; o < FEAT; ++o)
            s = fmaf(lin_w[o], conv_w[o * (FEAT * KW) + j], s);
        g_weff[j] = s;
    }
    if (blockIdx.x == 0) {
        __shared__ float sh[256];
        sh[threadIdx.x] = conv_b[threadIdx.x] * lin_w[threadIdx.x];
        __syncthreads();
        for (int ofs = 128; ofs > 0; ofs >>= 1) {
            if ((int)threadIdx.x < ofs) sh[threadIdx.x] += sh[threadIdx.x + ofs];
            __syncthreads();
        }
        if (threadIdx.x == 0) g_bias = sh[0] + lin_b[0];
    }
}

// ---------------------------------------------------------------------------
// Kernel 2: p[row][k] = dot(x[row,:], w_eff[:,k]) for k=0..4.
// One warp per group of 8 rows; each lane owns 8 fixed channels, so its 40
// weights are loaded once into registers and reused across all its rows.
// ---------------------------------------------------------------------------
__global__ __launch_bounds__(256) void pk_kernel(const float* __restrict__ x) {
    int warp_global = (blockIdx.x * blockDim.x + threadIdx.x) >> 5;  // 0..8191
    int lane = threadIdx.x & 31;
    int c0 = lane * 4;

    // Per-lane weights: channels c0..c0+3 and c0+128..c0+131, each x 5 taps.
    float w[8][KW];
#pragma unroll
    for (int j = 0; j < 8; ++j) {
        int c = (j < 4) ? (c0 + j) : (c0 + 124 + j);  // j=4..7 -> c0+128..c0+131
#pragma unroll
        for (int k = 0; k < KW; ++k) w[j][k] = g_weff[c * KW + k];
    }

    long row0 = (long)warp_global * 8;
    for (int r = 0; r < 8; ++r) {
        long row = row0 + r;
        const float4* r4 = (const float4*)(x + row * FEAT);
        float4 va = r4[lane];
        float4 vb = r4[lane + 32];
        float xs[8] = {va.x, va.y, va.z, va.w, vb.x, vb.y, vb.z, vb.w};
        float s[KW] = {0.f, 0.f, 0.f, 0.f, 0.f};
#pragma unroll
        for (int j = 0; j < 8; ++j)
#pragma unroll
            for (int k = 0; k < KW; ++k)
                s[k] = fmaf(xs[j], w[j][k], s[k]);
#pragma unroll
        for (int k = 0; k < KW; ++k)
#pragma unroll
            for (int ofs = 16; ofs > 0; ofs >>= 1)
                s[k] += __shfl_xor_sync(0xffffffffu, s[k], ofs);
        if (lane == 0) {
#pragma unroll
            for (int k = 0; k < KW; ++k) g_p[row * KW + k] = s[k];
        }
    }
}

// ---------------------------------------------------------------------------
// Kernel 3: alphas[b,t] = sigmoid( bias + sum_k p[b, t+k-2, k] )  (SAME pad)
// ---------------------------------------------------------------------------
__global__ void alpha_kernel() {
    int i = blockIdx.x * blockDim.x + threadIdx.x;   // i = b*T + t
    if (i >= BB * TT) return;
    int t = i & (TT - 1);
    float s = g_bias;
#pragma unroll
    for (int k = 0; k < KW; ++k) {
        int tt = t + k - 2;
        if (tt >= 0 && tt < TT) s += g_p[(long)(i + k - 2) * KW + k];
    }
    g_alphas[i] = 1.f / (1.f + expf(-s));
}

// ---------------------------------------------------------------------------
// Kernel 4: integrate-and-fire scan. One block per batch, thread d owns
// feature d. Scalar state replicated per-thread (uniform branch-free chain);
// x rows + alphas prefetched 8 steps ahead.
// ---------------------------------------------------------------------------
__global__ __launch_bounds__(FEAT) void scan_kernel(const float* __restrict__ x,
                                                    float* __restrict__ out,
                                                    float* __restrict__ lens,
                                                    int write_len) {
    int b = blockIdx.x;
    int d = threadIdx.x;
    const float* xb = x + (long)b * TT * FEAT;
    const float* ab = g_alphas + (long)b * TT;
    float* ob = out + (long)b * TT * FEAT;

    float acc = 0.f;
    float hacc = 0.f;
    int idx = 0;

    for (int t0 = 0; t0 < TT; t0 += 8) {
        // Prefetch 8 alphas (uniform broadcast) + 8 x-values (coalesced).
        float4 a0 = *(const float4*)(ab + t0);
        float4 a1v = *(const float4*)(ab + t0 + 4);
        float av[8] = {a0.x, a0.y, a0.z, a0.w, a1v.x, a1v.y, a1v.z, a1v.w};
        float hu[8];
#pragma unroll
        for (int i = 0; i < 8; ++i) hu[i] = xb[(long)(t0 + i) * FEAT + d];

#pragma unroll
        for (int i = 0; i < 8; ++i) {
            float a       = av[i];
            float h       = hu[i];
            float acc_new = acc + a;        // reference op order
            float a1      = 1.0f - acc;
            float a2      = a - a1;
            bool  fire    = (acc_new >= 1.0f);   // BETA = 1.0

            float c        = fmaf(a1, h, hacc);      // emitted segment vector
            float hacc_f   = a2 * h;
            float hacc_nf  = fmaf(a, h, hacc);

            if (fire) ob[(long)idx * FEAT + d] = c;  // predicated store
            idx += fire ? 1 : 0;
            hacc = fire ? hacc_f : hacc_nf;
            acc  = fire ? a2 : acc_new;
        }
    }

    if (idx == 0) ob[d] = hacc;            // n==0 fallback (reference semantics)
    if (write_len && d == 0) lens[b] = (float)(idx > 0 ? idx : 1);
}

// ---------------------------------------------------------------------------
extern "C" void kernel_launch(void* const* d_in, const int* in_sizes, int n_in,
                              void* d_out, int out_size) {
    const float* x      = (const float*)d_in[0];
    const float* conv_w = (const float*)d_in[1];
    const float* conv_b = (const float*)d_in[2];
    const float* lin_w  = (const float*)d_in[3];
    const float* lin_b  = (const float*)d_in[4];
    float* out = (float*)d_out;

    // Rows >= n must be exactly zero (output poisoned to 0xAA by harness).
    cudaMemsetAsync(d_out, 0, (size_t)out_size * sizeof(float), 0);

    fold_kernel<<<5, 256>>>(conv_w, conv_b, lin_w, lin_b);
    pk_kernel<<<1024, 256>>>(x);                       // 8192 warps x 8 rows
    alpha_kernel<<<(BB * TT + 255) / 256, 256>>>();

    int write_len = (out_size >= BB * TT * FEAT + BB) ? 1 : 0;
    float* lens = out + (size_t)BB * TT * FEAT;
    scan_kernel<<<BB, FEAT>>>(x, out, lens, write_len);
}

// round 2
// speedup vs baseline: 1.7344x; 1.7344x over previous
#include <cuda_runtime.h>

#define BB   16
#define TT   4096
#define FEAT 256
#define KW   5

// Scratch (no allocations allowed).
__device__ float g_weff[FEAT * KW];
__device__ float g_bias;
__device__ float g_p[BB * TT * KW];
__device__ float g_alphas[BB * TT];
__device__ float g_wend[BB * TT];    // a1 at fire rows (segment-end weight)
__device__ float g_wstart[BB * TT];  // a2 at fire rows (next-segment-start weight)
__device__ int   g_ft[BB * TT];      // fire times per batch (dense)
__device__ int   g_n[BB];            // segment counts

// ---------------------------------------------------------------------------
// Kernel 1: fold lin_w into conv_w  ->  w_eff[c,k] = sum_o lin_w[o]*conv_w[o,c,k]
// ---------------------------------------------------------------------------
__global__ void fold_kernel(const float* __restrict__ conv_w,
                            const float* __restrict__ conv_b,
                            const float* __restrict__ lin_w,
                            const float* __restrict__ lin_b) {
    int j = blockIdx.x * blockDim.x + threadIdx.x;   // j = c*KW + k
    if (j < FEAT * KW) {
        float s = 0.f;
#pragma unroll 4
        for (int o = 0; o < FEAT; ++o)
            s = fmaf(lin_w[o], conv_w[o * (FEAT * KW) + j], s);
        g_weff[j] = s;
    }
    if (blockIdx.x == 0) {
        __shared__ float sh[256];
        sh[threadIdx.x] = conv_b[threadIdx.x] * lin_w[threadIdx.x];
        __syncthreads();
        for (int ofs = 128; ofs > 0; ofs >>= 1) {
            if ((int)threadIdx.x < ofs) sh[threadIdx.x] += sh[threadIdx.x + ofs];
            __syncthreads();
        }
        if (threadIdx.x == 0) g_bias = sh[0] + lin_b[0];
    }
}

// ---------------------------------------------------------------------------
// Kernel 2: p[row][k] = dot(x[row,:], w_eff[:,k]) for k=0..4.
// ---------------------------------------------------------------------------
__global__ __launch_bounds__(256) void pk_kernel(const float* __restrict__ x) {
    int warp_global = (blockIdx.x * blockDim.x + threadIdx.x) >> 5;  // 0..8191
    int lane = threadIdx.x & 31;
    int c0 = lane * 4;

    float w[8][KW];
#pragma unroll
    for (int j = 0; j < 8; ++j) {
        int c = (j < 4) ? (c0 + j) : (c0 + 124 + j);
#pragma unroll
        for (int k = 0; k < KW; ++k) w[j][k] = g_weff[c * KW + k];
    }

    long row0 = (long)warp_global * 8;
    for (int r = 0; r < 8; ++r) {
        long row = row0 + r;
        const float4* r4 = (const float4*)(x + row * FEAT);
        float4 va = r4[lane];
        float4 vb = r4[lane + 32];
        float xs[8] = {va.x, va.y, va.z, va.w, vb.x, vb.y, vb.z, vb.w};
        float s[KW] = {0.f, 0.f, 0.f, 0.f, 0.f};
#pragma unroll
        for (int j = 0; j < 8; ++j)
#pragma unroll
            for (int k = 0; k < KW; ++k)
                s[k] = fmaf(xs[j], w[j][k], s[k]);
#pragma unroll
        for (int k = 0; k < KW; ++k)
#pragma unroll
            for (int ofs = 16; ofs > 0; ofs >>= 1)
                s[k] += __shfl_xor_sync(0xffffffffu, s[k], ofs);
        if (lane == 0) {
#pragma unroll
            for (int k = 0; k < KW; ++k) g_p[row * KW + k] = s[k];
        }
    }
}

// ---------------------------------------------------------------------------
// Kernel 3: alphas[b,t] = sigmoid( bias + sum_k p[b, t+k-2, k] )  (SAME pad)
// ---------------------------------------------------------------------------
__global__ void alpha_kernel() {
    int i = blockIdx.x * blockDim.x + threadIdx.x;   // i = b*T + t
    if (i >= BB * TT) return;
    int t = i & (TT - 1);
    float s = g_bias;
#pragma unroll
    for (int k = 0; k < KW; ++k) {
        int tt = t + k - 2;
        if (tt >= 0 && tt < TT) s += g_p[(long)(i + k - 2) * KW + k];
    }
    g_alphas[i] = 1.f / (1.f + expf(-s));
}

// ---------------------------------------------------------------------------
// Kernel 4: sequential alpha scan (the ONLY sequential part). 16 lanes, one
// per batch. Exact reference op order so fire decisions match bit-for-bit.
// Emits fire times + boundary weights; bulk h never touched here.
// ---------------------------------------------------------------------------
#define STEP(aval, tcur) do {                                   \
    float a = (aval);                                           \
    float acc_new = acc + a;                                    \
    float a1 = 1.0f - acc;                                      \
    float a2 = a - a1;                                          \
    bool fire = (acc_new >= 1.0f);                              \
    if (fire) {                                                 \
        g_wend[wbase + (tcur)] = a1;                            \
        g_wstart[wbase + (tcur)] = a2;                          \
        g_ft[wbase + n] = (tcur);                               \
        ++n;                                                    \
    }                                                           \
    acc = fire ? a2 : acc_new;                                  \
} while (0)

__global__ void seq_scan_kernel(float* __restrict__ lens, int write_len) {
    int b = threadIdx.x;
    if (b >= BB) return;
    const float* ab = g_alphas + (size_t)b * TT;
    const int wbase = b * TT;
    float acc = 0.f;
    int n = 0;

    float bufA[32], bufB[32];
#pragma unroll
    for (int i = 0; i < 8; ++i)
        ((float4*)bufA)[i] = ((const float4*)ab)[i];

    for (int t0 = 0; t0 < TT; t0 += 64) {
        // prefetch next 32 while processing current 32
#pragma unroll
        for (int i = 0; i < 8; ++i)
            ((float4*)bufB)[i] = ((const float4*)(ab + t0 + 32))[i];
#pragma unroll
        for (int i = 0; i < 32; ++i) STEP(bufA[i], t0 + i);
        if (t0 + 64 < TT) {
#pragma unroll
            for (int i = 0; i < 8; ++i)
                ((float4*)bufA)[i] = ((const float4*)(ab + t0 + 64))[i];
        }
#pragma unroll
        for (int i = 0; i < 32; ++i) STEP(bufB[i], t0 + 32 + i);
    }

    if (n == 0) {
        // no fire: emit final accumulator as single pseudo-segment over all T
        g_wend[wbase + TT - 1] = ab[TT - 1];
        g_ft[wbase] = TT - 1;
        n = 1;
    }
    g_n[b] = n;
    if (write_len) lens[b] = (float)n;
}

// ---------------------------------------------------------------------------
// Kernel 5: parallel emission. Segment j spans (ft[j-1], ft[j]]; per-segment
// accumulation order matches the reference scan exactly.
// ---------------------------------------------------------------------------
__global__ __launch_bounds__(FEAT) void emit_kernel(const float* __restrict__ x,
                                                    float* __restrict__ out) {
    int b = blockIdx.x;
    int d = threadIdx.x;
    int n = g_n[b];
    const float* xb = x + (size_t)b * TT * FEAT;
    const float* ab = g_alphas + (size_t)b * TT;
    const int wbase = b * TT;
    float* ob = out + (size_t)b * TT * FEAT;

    for (int j = blockIdx.y; j < n; j += gridDim.y) {
        int e = g_ft[wbase + j];
        float accv;
        int u0;
        if (j == 0) {
            accv = 0.f;
            u0 = 0;
        } else {
            int s = g_ft[wbase + j - 1];
            accv = g_wstart[wbase + s] * xb[(size_t)s * FEAT + d];
            u0 = s + 1;
        }
        for (int u = u0; u < e; ++u)
            accv = fmaf(ab[u], xb[(size_t)u * FEAT + d], accv);
        accv = fmaf(g_wend[wbase + e], xb[(size_t)e * FEAT + d], accv);
        ob[(size_t)j * FEAT + d] = accv;
    }
}

// ---------------------------------------------------------------------------
// Kernel 6: zero only the tail rows (j >= n) instead of a full-buffer memset.
// ---------------------------------------------------------------------------
__global__ __launch_bounds__(256) void zero_tail_kernel(float* __restrict__ out) {
    int b = blockIdx.x;
    int n = g_n[b];
    float4* ob = (float4*)(out + (size_t)b * TT * FEAT);
    const int total_v4 = TT * (FEAT / 4);
    int start = n * (FEAT / 4);
    float4 z = make_float4(0.f, 0.f, 0.f, 0.f);
    for (int i = start + blockIdx.y * blockDim.x + threadIdx.x; i < total_v4;
         i += gridDim.y * blockDim.x)
        ob[i] = z;
}

// ---------------------------------------------------------------------------
extern "C" void kernel_launch(void* const* d_in, const int* in_sizes, int n_in,
                              void* d_out, int out_size) {
    const float* x      = (const float*)d_in[0];
    const float* conv_w = (const float*)d_in[1];
    const float* conv_b = (const float*)d_in[2];
    const float* lin_w  = (const float*)d_in[3];
    const float* lin_b  = (const float*)d_in[4];
    float* out = (float*)d_out;

    // Zero only the slack region past the dense output (lens etc.); dense
    // rows are covered by emit_kernel (j < n) + zero_tail_kernel (j >= n).
    const size_t dense = (size_t)BB * TT * FEAT;
    if ((size_t)out_size > dense)
        cudaMemsetAsync(out + dense, 0, ((size_t)out_size - dense) * sizeof(float), 0);

    fold_kernel<<<5, 256>>>(conv_w, conv_b, lin_w, lin_b);
    pk_kernel<<<1024, 256>>>(x);
    alpha_kernel<<<(BB * TT + 255) / 256, 256>>>();

    int write_len = (out_size >= BB * TT * FEAT + BB) ? 1 : 0;
    float* lens = out + dense;
    seq_scan_kernel<<<1, 32>>>(lens, write_len);

    dim3 eg(BB, 128);
    emit_kernel<<<eg, FEAT>>>(x, out);
    zero_tail_kernel<<<dim3(BB, 128), 256>>>(out);
}

// round 3
// speedup vs baseline: 2.3222x; 1.3390x over previous
#include <cuda_runtime.h>

#define BB   16
#define TT   4096
#define FEAT 256
#define KW   5
#define NCHUNK (TT / 32)   // 128 mask words per batch

// Scratch (no allocations allowed).
__device__ float  g_weff[FEAT * KW];
__device__ float  g_bias;
__device__ float  g_p[BB * TT * KW];
__device__ float  g_alphas[BB * TT];
__device__ float2 g_w[TT * BB];          // (a1, a2) transposed: [t*BB + b]
__device__ unsigned g_mask[BB * NCHUNK]; // fire bitmasks
__device__ int    g_ft[BB * TT];         // fire times (dense per batch)
__device__ int2   g_seg[BB * TT];        // (prev_fire_row or -1, fire_row)
__device__ int    g_n[BB];

// ---------------------------------------------------------------------------
// Kernel 1: fold lin_w into conv_w  ->  w_eff[c,k] = sum_o lin_w[o]*conv_w[o,c,k]
// ---------------------------------------------------------------------------
__global__ void fold_kernel(const float* __restrict__ conv_w,
                            const float* __restrict__ conv_b,
                            const float* __restrict__ lin_w,
                            const float* __restrict__ lin_b) {
    int j = blockIdx.x * blockDim.x + threadIdx.x;   // j = c*KW + k
    if (j < FEAT * KW) {
        float s = 0.f;
#pragma unroll 4
        for (int o = 0; o < FEAT; ++o)
            s = fmaf(lin_w[o], conv_w[o * (FEAT * KW) + j], s);
        g_weff[j] = s;
    }
    if (blockIdx.x == 0) {
        __shared__ float sh[256];
        sh[threadIdx.x] = conv_b[threadIdx.x] * lin_w[threadIdx.x];
        __syncthreads();
        for (int ofs = 128; ofs > 0; ofs >>= 1) {
            if ((int)threadIdx.x < ofs) sh[threadIdx.x] += sh[threadIdx.x + ofs];
            __syncthreads();
        }
        if (threadIdx.x == 0) g_bias = sh[0] + lin_b[0];
    }
}

// ---------------------------------------------------------------------------
// Kernel 2: p[row][k] = dot(x[row,:], w_eff[:,k]) for k=0..4.
// ---------------------------------------------------------------------------
__global__ __launch_bounds__(256) void pk_kernel(const float* __restrict__ x) {
    int warp_global = (blockIdx.x * blockDim.x + threadIdx.x) >> 5;  // 0..8191
    int lane = threadIdx.x & 31;
    int c0 = lane * 4;

    float w[8][KW];
#pragma unroll
    for (int j = 0; j < 8; ++j) {
        int c = (j < 4) ? (c0 + j) : (c0 + 124 + j);
#pragma unroll
        for (int k = 0; k < KW; ++k) w[j][k] = g_weff[c * KW + k];
    }

    long row0 = (long)warp_global * 8;
    for (int r = 0; r < 8; ++r) {
        long row = row0 + r;
        const float4* r4 = (const float4*)(x + row * FEAT);
        float4 va = r4[lane];
        float4 vb = r4[lane + 32];
        float xs[8] = {va.x, va.y, va.z, va.w, vb.x, vb.y, vb.z, vb.w};
        float s[KW] = {0.f, 0.f, 0.f, 0.f, 0.f};
#pragma unroll
        for (int j = 0; j < 8; ++j)
#pragma unroll
            for (int k = 0; k < KW; ++k)
                s[k] = fmaf(xs[j], w[j][k], s[k]);
#pragma unroll
        for (int k = 0; k < KW; ++k)
#pragma unroll
            for (int ofs = 16; ofs > 0; ofs >>= 1)
                s[k] += __shfl_xor_sync(0xffffffffu, s[k], ofs);
        if (lane == 0) {
#pragma unroll
            for (int k = 0; k < KW; ++k) g_p[row * KW + k] = s[k];
        }
    }
}

// ---------------------------------------------------------------------------
// Kernel 3: alphas[b,t] = sigmoid( bias + sum_k p[b, t+k-2, k] )  (SAME pad)
// ---------------------------------------------------------------------------
__global__ void alpha_kernel() {
    int i = blockIdx.x * blockDim.x + threadIdx.x;   // i = b*T + t
    if (i >= BB * TT) return;
    int t = i & (TT - 1);
    float s = g_bias;
#pragma unroll
    for (int k = 0; k < KW; ++k) {
        int tt = t + k - 2;
        if (tt >= 0 && tt < TT) s += g_p[(long)(i + k - 2) * KW + k];
    }
    g_alphas[i] = 1.f / (1.f + expf(-s));
}

// ---------------------------------------------------------------------------
// Kernel 4: sequential alpha scan — branch-free. 16 lanes, one per batch.
// Exact reference op order so fire decisions match. Per step: 12-cyc
// FADD->FSETP->FSEL chain, one coalesced STG.64 (transposed (a1,a2)),
// fire bit accumulated into a register mask stored once per 32 steps.
// ---------------------------------------------------------------------------
__global__ void seq_scan_kernel() {
    int b = threadIdx.x;
    if (b >= BB) return;
    const float* ab = g_alphas + (size_t)b * TT;
    float acc = 0.f;

    float bufA[32], bufB[32];
#pragma unroll
    for (int i = 0; i < 8; ++i)
        ((float4*)bufA)[i] = ((const float4*)ab)[i];

    for (int t0 = 0; t0 < TT; t0 += 64) {
        // prefetch next 32 while processing current 32
#pragma unroll
        for (int i = 0; i < 8; ++i)
            ((float4*)bufB)[i] = ((const float4*)(ab + t0 + 32))[i];

        unsigned maskA = 0u;
#pragma unroll
        for (int i = 0; i < 32; ++i) {
            float a       = bufA[i];
            float acc_new = acc + a;
            float a1      = 1.0f - acc;
            float a2      = a - a1;
            bool  fire    = (acc_new >= 1.0f);
            g_w[(t0 + i) * BB + b] = make_float2(a1, a2);
            maskA |= fire ? (1u << i) : 0u;
            acc = fire ? a2 : acc_new;
        }
        g_mask[b * NCHUNK + (t0 >> 5)] = maskA;

        if (t0 + 64 < TT) {
#pragma unroll
            for (int i = 0; i < 8; ++i)
                ((float4*)bufA)[i] = ((const float4*)(ab + t0 + 64))[i];
        }

        unsigned maskB = 0u;
#pragma unroll
        for (int i = 0; i < 32; ++i) {
            float a       = bufB[i];
            float acc_new = acc + a;
            float a1      = 1.0f - acc;
            float a2      = a - a1;
            bool  fire    = (acc_new >= 1.0f);
            g_w[(t0 + 32 + i) * BB + b] = make_float2(a1, a2);
            maskB |= fire ? (1u << i) : 0u;
            acc = fire ? a2 : acc_new;
        }
        g_mask[b * NCHUNK + (t0 >> 5) + 1] = maskB;
    }
}

// ---------------------------------------------------------------------------
// Kernel 5: compaction. One block per batch, 128 threads (one mask word each).
// Builds fire-time list, segment table (prev_fire, fire), n, lens.
// ---------------------------------------------------------------------------
__global__ __launch_bounds__(128) void compact_kernel(float* __restrict__ lens,
                                                      int write_len) {
    int b = blockIdx.x;
    int t = threadIdx.x;
    __shared__ int pre[129];

    unsigned m = g_mask[b * NCHUNK + t];
    int cnt = __popc(m);

    // block-wide exclusive prefix (Hillis-Steele over 128)
    __shared__ int tmp[128];
    tmp[t] = cnt;
    __syncthreads();
    for (int ofs = 1; ofs < 128; ofs <<= 1) {
        int v = (t >= ofs) ? tmp[t - ofs] : 0;
        __syncthreads();
        tmp[t] += v;
        __syncthreads();
    }
    pre[t + 1] = tmp[t];
    if (t == 0) pre[0] = 0;
    __syncthreads();

    int n = pre[128];
    const int wbase = b * TT;

    // scatter fire times in order
    int rank = pre[t];
    unsigned mm = m;
    while (mm) {
        int i = __ffs(mm) - 1;
        mm &= mm - 1;
        g_ft[wbase + rank] = t * 32 + i;
        ++rank;
    }
    __syncthreads();

    if (n == 0) {
        // no fire: single pseudo-segment covering all T; final hacc is the
        // in-order sum a_t*h_t, realised by setting wend[T-1] = alpha[T-1].
        if (t == 0) {
            g_ft[wbase] = TT - 1;
            g_seg[wbase] = make_int2(-1, TT - 1);
            g_w[(TT - 1) * BB + b].x = g_alphas[(size_t)b * TT + TT - 1];
            g_n[b] = 1;
            if (write_len) lens[b] = 1.0f;
        }
        return;
    }

    // build segment table
    for (int j = t; j < n; j += 128) {
        int s = (j == 0) ? -1 : g_ft[wbase + j - 1];
        g_seg[wbase + j] = make_int2(s, g_ft[wbase + j]);
    }
    if (t == 0) {
        g_n[b] = n;
        if (write_len) lens[b] = (float)n;
    }
}

// ---------------------------------------------------------------------------
// Kernel 6: fused emission + tail zero. Rows j < n: weighted sum over the
// segment (reference accumulation order). Rows j >= n: zeros.
// ---------------------------------------------------------------------------
__global__ __launch_bounds__(FEAT) void emit_kernel(const float* __restrict__ x,
                                                    float* __restrict__ out) {
    int b = blockIdx.x;
    int d = threadIdx.x;
    int n = g_n[b];
    const float* xb = x + (size_t)b * TT * FEAT;
    const float* ab = g_alphas + (size_t)b * TT;
    const int wbase = b * TT;
    float* ob = out + (size_t)b * TT * FEAT;

    for (int j = blockIdx.y; j < TT; j += gridDim.y) {
        if (j >= n) {
            ob[(size_t)j * FEAT + d] = 0.f;
            continue;
        }
        int2 se = g_seg[wbase + j];
        float accv = 0.f;
        int u0 = 0;
        if (se.x >= 0) {
            accv = g_w[se.x * BB + b].y * xb[(size_t)se.x * FEAT + d];
            u0 = se.x + 1;
        }
        for (int u = u0; u < se.y; ++u)
            accv = fmaf(ab[u], xb[(size_t)u * FEAT + d], accv);
        accv = fmaf(g_w[se.y * BB + b].x, xb[(size_t)se.y * FEAT + d], accv);
        ob[(size_t)j * FEAT + d] = accv;
    }
}

// ---------------------------------------------------------------------------
extern "C" void kernel_launch(void* const* d_in, const int* in_sizes, int n_in,
                              void* d_out, int out_size) {
    const float* x      = (const float*)d_in[0];
    const float* conv_w = (const float*)d_in[1];
    const float* conv_b = (const float*)d_in[2];
    const float* lin_w  = (const float*)d_in[3];
    const float* lin_b  = (const float*)d_in[4];
    float* out = (float*)d_out;

    // Zero only the slack region past the dense output (lens etc.).
    const size_t dense = (size_t)BB * TT * FEAT;
    if ((size_t)out_size > dense)
        cudaMemsetAsync(out + dense, 0, ((size_t)out_size - dense) * sizeof(float), 0);

    fold_kernel<<<5, 256>>>(conv_w, conv_b, lin_w, lin_b);
    pk_kernel<<<1024, 256>>>(x);
    alpha_kernel<<<(BB * TT + 255) / 256, 256>>>();

    seq_scan_kernel<<<1, 32>>>();

    int write_len = (out_size >= BB * TT * FEAT + BB) ? 1 : 0;
    float* lens = out + dense;
    compact_kernel<<<BB, 128>>>(lens, write_len);

    emit_kernel<<<dim3(BB, 256), FEAT>>>(x, out);
}